// round 2
// baseline (speedup 1.0000x reference)
#include <cuda_runtime.h>
#include <cuda_bf16.h>
#include <cstdint>

#define THREADS 512
static constexpr int BATCH  = 131072;
static constexpr int DDIM   = 128;
static constexpr int TILE_M = 128;
static constexpr int NTILES = BATCH / TILE_M;   // 1024
static constexpr int PITCH  = 272;              // 128 bf16 (256B) + 16B pad -> conflict-free ldmatrix

// ---- SMEM layout (bytes) ----
static constexpr int SM_A_HI = 0;               // state tile hi : 128 x PITCH = 34816
static constexpr int SM_A_LO = 34816;
static constexpr int SM_B_HI = 69632;           // W (256 cols)  : 256 x PITCH = 69632
static constexpr int SM_B_LO = 139264;
static constexpr int SM_BIAS = 208896;          // 256 floats
static constexpr int SMEM_TOTAL = 208896 + 1024;

// ---------------- helpers ----------------
__device__ __forceinline__ uint32_t smem_u32(const void* p){
    uint32_t a;
    asm("{ .reg .u64 t; cvta.to.shared.u64 t, %1; cvt.u32.u64 %0, t; }" : "=r"(a) : "l"(p));
    return a;
}
__device__ __forceinline__ uint32_t packbf(float hi, float lo){
    uint32_t r; asm("cvt.rn.bf16x2.f32 %0, %1, %2;" : "=r"(r) : "f"(hi), "f"(lo)); return r;
}
__device__ __forceinline__ void ldsm4(uint32_t* r, uint32_t addr){
    asm volatile("ldmatrix.sync.aligned.m8n8.x4.shared.b16 {%0,%1,%2,%3}, [%4];"
        : "=r"(r[0]), "=r"(r[1]), "=r"(r[2]), "=r"(r[3]) : "r"(addr));
}
__device__ __forceinline__ void mma16816(float* c, const uint32_t* a, uint32_t b0, uint32_t b1){
    asm("mma.sync.aligned.m16n8k16.row.col.f32.bf16.bf16.f32 "
        "{%0,%1,%2,%3}, {%4,%5,%6,%7}, {%8,%9}, {%0,%1,%2,%3};"
        : "+f"(c[0]), "+f"(c[1]), "+f"(c[2]), "+f"(c[3])
        : "r"(a[0]), "r"(a[1]), "r"(a[2]), "r"(a[3]), "r"(b0), "r"(b1));
}

// ---------------- tile helpers ----------------
__device__ __forceinline__ void prefetch_tile(const float* __restrict__ state, int t, int tid, float4* v){
    const float4* p = reinterpret_cast<const float4*>(state) + (size_t)t * (TILE_M * DDIM / 4);
    #pragma unroll
    for (int k = 0; k < 8; k++) v[k] = p[tid + THREADS * k];
}

// hi/lo bf16 split of the 128x128 fp32 state tile into A_hi / A_lo smem (row pitch 272B).
__device__ __forceinline__ void convert_tile(char* sm, int tid, const float4* v){
    #pragma unroll
    for (int k = 0; k < 8; k++){
        int j  = tid + THREADS * k;           // float4 index within tile
        int r  = j >> 5;                      // row (32 float4 per row)
        int cb = (j & 31) * 8;                // byte col within 256B of bf16 data
        uint32_t off = (uint32_t)r * PITCH + cb;
        float4 f = v[k];
        uint32_t h0 = packbf(f.y, f.x);
        uint32_t h1 = packbf(f.w, f.z);
        float rx = f.x - __uint_as_float(h0 << 16);
        float ry = f.y - __uint_as_float(h0 & 0xFFFF0000u);
        float rz = f.z - __uint_as_float(h1 << 16);
        float rw = f.w - __uint_as_float(h1 & 0xFFFF0000u);
        uint32_t l0 = packbf(ry, rx);
        uint32_t l1 = packbf(rw, rz);
        *reinterpret_cast<uint2*>(sm + SM_A_HI + off) = make_uint2(h0, h1);
        *reinterpret_cast<uint2*>(sm + SM_A_LO + off) = make_uint2(l0, l1);
    }
}

// ---------------- kernel ----------------
__global__ void __launch_bounds__(THREADS, 1)
lfm_kernel(const float* __restrict__ state, const float* __restrict__ Wt,
           const float* __restrict__ bias,  float* __restrict__ out)
{
    extern __shared__ char sm[];
    uint32_t sbase = smem_u32(sm);
    const int tid  = threadIdx.x;
    const int wid  = tid >> 5;
    const int lane = tid & 31;
    const int wm   = wid & 3;       // warp m-block (32 rows each)
    const int wn   = wid >> 2;      // warp n-block (64 cols each)

    // ---- one-time: convert W[n][o][d] -> B smem rows (col index = o*128+n, k=d), bias to smem ----
    for (int idx = tid; idx < 128 * 128; idx += THREADS){
        int n = idx >> 7, d = idx & 127;
        #pragma unroll
        for (int o = 0; o < 2; o++){
            float w = Wt[(size_t)n * 256 + o * 128 + d];
            __nv_bfloat16 h = __float2bfloat16(w);
            __nv_bfloat16 l = __float2bfloat16(w - __bfloat162float(h));
            uint32_t off = (uint32_t)(o * 128 + n) * PITCH + d * 2;
            *reinterpret_cast<__nv_bfloat16*>(sm + SM_B_HI + off) = h;
            *reinterpret_cast<__nv_bfloat16*>(sm + SM_B_LO + off) = l;
        }
    }
    for (int idx = tid; idx < 256; idx += THREADS){
        int o = idx >> 7, n = idx & 127;
        reinterpret_cast<float*>(sm + SM_BIAS)[idx] = bias[n * 2 + o];
    }

    // per-lane ldmatrix sub-offsets (derived from PTX fragment layouts)
    const uint32_t aoff = (uint32_t)((lane & 7) + ((lane >> 3) & 1) * 8) * PITCH + ((lane >> 4) & 1) * 16;
    const uint32_t boff = (uint32_t)((lane & 7) + ((lane >> 4) & 1) * 8) * PITCH + ((lane >> 3) & 1) * 16;
    const uint32_t baseAhi = sbase + SM_A_HI + (uint32_t)(wm * 32) * PITCH + aoff;
    const uint32_t baseAlo = sbase + SM_A_LO + (uint32_t)(wm * 32) * PITCH + aoff;
    const uint32_t baseBhi = sbase + SM_B_HI + (uint32_t)(wn * 64) * PITCH + boff;
    const uint32_t baseBlo = sbase + SM_B_LO + (uint32_t)(wn * 64) * PITCH + boff;

    const int bid = blockIdx.x, grid = gridDim.x;
    const int nt  = (NTILES - bid + grid - 1) / grid;   // >= 1 since grid <= NTILES

    // Prologue: load + convert first tile
    float4 v[8];
    prefetch_tile(state, bid, tid, v);
    convert_tile(sm, tid, v);
    __syncthreads();

    const float* bias_sm = reinterpret_cast<const float*>(sm + SM_BIAS);
    const size_t out_half = (size_t)BATCH * DDIM;

    for (int i = 0; i < nt; i++){
        const int  t   = bid + i * grid;
        const bool nxt = (i + 1) < nt;

        float acc[2][8][4];
        #pragma unroll
        for (int mt = 0; mt < 2; mt++)
            #pragma unroll
            for (int nj = 0; nj < 8; nj++)
                #pragma unroll
                for (int e = 0; e < 4; e++) acc[mt][nj][e] = 0.f;

        // ---- K loop: 8 steps of k16; 3-term bf16 split (hh + lh + hl) ----
        #pragma unroll
        for (int ks = 0; ks < 8; ks++){
            uint32_t ahi0[4], ahi1[4], alo0[4], alo1[4];
            ldsm4(ahi0, baseAhi + ks * 32);
            ldsm4(ahi1, baseAhi + 16 * PITCH + ks * 32);
            ldsm4(alo0, baseAlo + ks * 32);
            ldsm4(alo1, baseAlo + 16 * PITCH + ks * 32);
            #pragma unroll
            for (int np = 0; np < 4; np++){        // pairs of n8 tiles
                uint32_t bh[4], bl[4];
                ldsm4(bh, baseBhi + (uint32_t)(np * 16) * PITCH + ks * 32);
                ldsm4(bl, baseBlo + (uint32_t)(np * 16) * PITCH + ks * 32);
                // n-tile 2*np  : b regs {bh[0],bh[1]} / {bl[0],bl[1]}
                mma16816(acc[0][2*np],   ahi0, bh[0], bh[1]);
                mma16816(acc[1][2*np],   ahi1, bh[0], bh[1]);
                mma16816(acc[0][2*np],   alo0, bh[0], bh[1]);
                mma16816(acc[1][2*np],   alo1, bh[0], bh[1]);
                mma16816(acc[0][2*np],   ahi0, bl[0], bl[1]);
                mma16816(acc[1][2*np],   ahi1, bl[0], bl[1]);
                // n-tile 2*np+1: {bh[2],bh[3]} / {bl[2],bl[3]}
                mma16816(acc[0][2*np+1], ahi0, bh[2], bh[3]);
                mma16816(acc[1][2*np+1], ahi1, bh[2], bh[3]);
                mma16816(acc[0][2*np+1], alo0, bh[2], bh[3]);
                mma16816(acc[1][2*np+1], alo1, bh[2], bh[3]);
                mma16816(acc[0][2*np+1], ahi0, bl[2], bl[3]);
                mma16816(acc[1][2*np+1], ahi1, bl[2], bl[3]);
            }
        }

        // Prefetch next tile's state while the epilogue stores drain
        if (nxt) prefetch_tile(state, t + grid, tid, v);

        // ---- epilogue: bias + store. Warp covers rows [wm*32, +32), cols [wn*64, +64). ----
        {
            const int o      = wn >> 1;
            const int colw   = (wn & 1) * 64;                 // col within the 128-wide half
            const int rbase  = wm * 32 + (lane >> 2);
            float* outp = out + (o ? out_half : 0) + ((size_t)t * TILE_M) * DDIM;
            #pragma unroll
            for (int mt = 0; mt < 2; mt++){
                #pragma unroll
                for (int nj = 0; nj < 8; nj++){
                    const int cg  = colw + nj * 8 + 2 * (lane & 3);   // col in [0,128)
                    const int cgb = (wn & 1) * 64 + nj * 8 + 2 * (lane & 3) + (o << 7);
                    float b0 = bias_sm[cgb], b1 = bias_sm[cgb + 1];
                    float* p0 = outp + (size_t)(rbase + mt * 16) * DDIM + cg;
                    float* p1 = p0 + 8 * DDIM;
                    float2 s0 = make_float2(acc[mt][nj][0] + b0, acc[mt][nj][1] + b1);
                    float2 s1 = make_float2(acc[mt][nj][2] + b0, acc[mt][nj][3] + b1);
                    *reinterpret_cast<float2*>(p0) = s0;
                    *reinterpret_cast<float2*>(p1) = s1;
                }
            }
        }

        __syncthreads();                 // everyone done reading A smem
        if (nxt){
            convert_tile(sm, tid, v);    // refill A smem for tile t+grid
        }
        __syncthreads();
    }
}

extern "C" void kernel_launch(void* const* d_in, const int* in_sizes, int n_in,
                              void* d_out, int out_size){
    (void)in_sizes; (void)n_in; (void)out_size;
    const float* state = (const float*)d_in[0];
    const float* W     = (const float*)d_in[1];
    const float* b     = (const float*)d_in[2];
    float* out = (float*)d_out;

    int dev = 0, sms = 148;
    cudaGetDevice(&dev);
    cudaDeviceGetAttribute(&sms, cudaDevAttrMultiProcessorCount, dev);
    if (sms < 1) sms = 148;
    if (sms > NTILES) sms = NTILES;

    cudaFuncSetAttribute(lfm_kernel, cudaFuncAttributeMaxDynamicSharedMemorySize, SMEM_TOTAL);
    lfm_kernel<<<sms, THREADS, SMEM_TOTAL>>>(state, W, b, out);
}

// round 3
// speedup vs baseline: 1.1703x; 1.1703x over previous
#include <cuda_runtime.h>
#include <cuda_fp16.h>
#include <cstdint>

#define THREADS 512
static constexpr int BATCH  = 131072;
static constexpr int DDIM   = 128;
static constexpr int TILE_M = 128;
static constexpr int NTILES = BATCH / TILE_M;   // 1024
static constexpr int PITCH  = 272;              // 128 fp16 (256B) + 16B pad -> conflict-free ldmatrix

// ---- SMEM layout (bytes). A double-buffered (hi/lo per buffer); B single fp16. ----
static constexpr int SM_A0_H = 0;               // 128 x PITCH = 34816
static constexpr int SM_A0_L = 34816;
static constexpr int SM_A1_H = 69632;
static constexpr int SM_A1_L = 104448;
static constexpr int SM_B    = 139264;          // 256 x PITCH = 69632
static constexpr int SM_BIAS = 208896;          // 256 floats
static constexpr int SMEM_TOTAL = 208896 + 1024;

// ---------------- helpers ----------------
__device__ __forceinline__ uint32_t smem_u32(const void* p){
    uint32_t a;
    asm("{ .reg .u64 t; cvta.to.shared.u64 t, %1; cvt.u32.u64 %0, t; }" : "=r"(a) : "l"(p));
    return a;
}
__device__ __forceinline__ void ldsm4(uint32_t* r, uint32_t addr){
    asm volatile("ldmatrix.sync.aligned.m8n8.x4.shared.b16 {%0,%1,%2,%3}, [%4];"
        : "=r"(r[0]), "=r"(r[1]), "=r"(r[2]), "=r"(r[3]) : "r"(addr));
}
__device__ __forceinline__ void mma16816(float* c, const uint32_t* a, uint32_t b0, uint32_t b1){
    asm("mma.sync.aligned.m16n8k16.row.col.f32.f16.f16.f32 "
        "{%0,%1,%2,%3}, {%4,%5,%6,%7}, {%8,%9}, {%0,%1,%2,%3};"
        : "+f"(c[0]), "+f"(c[1]), "+f"(c[2]), "+f"(c[3])
        : "r"(a[0]), "r"(a[1]), "r"(a[2]), "r"(a[3]), "r"(b0), "r"(b1));
}
__device__ __forceinline__ uint32_t pack_h2(float lo, float hi){
    __half2 h = __floats2half2_rn(lo, hi);
    return *reinterpret_cast<uint32_t*>(&h);
}
__device__ __forceinline__ float h2_lo(uint32_t u){ return __half2float(__ushort_as_half((unsigned short)(u & 0xFFFF))); }
__device__ __forceinline__ float h2_hi(uint32_t u){ return __half2float(__ushort_as_half((unsigned short)(u >> 16))); }

// ---------------- tile helpers ----------------
__device__ __forceinline__ void prefetch_tile(const float* __restrict__ state, int t, int tid, float4* v){
    const float4* p = reinterpret_cast<const float4*>(state) + (size_t)t * (TILE_M * DDIM / 4);
    #pragma unroll
    for (int k = 0; k < 8; k++) v[k] = p[tid + THREADS * k];
}

// fp16 hi/lo split of the 128x128 fp32 state tile into A_hi / A_lo smem (row pitch 272B).
__device__ __forceinline__ void convert_tile(char* sm, int buf, int tid, const float4* v){
    const int AH = buf ? SM_A1_H : SM_A0_H;
    const int AL = buf ? SM_A1_L : SM_A0_L;
    #pragma unroll
    for (int k = 0; k < 8; k++){
        int j  = tid + THREADS * k;           // float4 index within tile
        int r  = j >> 5;                      // row (32 float4 per row)
        int cb = (j & 31) * 8;                // byte col within 256B of fp16 data
        uint32_t off = (uint32_t)r * PITCH + cb;
        float4 f = v[k];
        uint32_t h0 = pack_h2(f.x, f.y);
        uint32_t h1 = pack_h2(f.z, f.w);
        uint32_t l0 = pack_h2(f.x - h2_lo(h0), f.y - h2_hi(h0));
        uint32_t l1 = pack_h2(f.z - h2_lo(h1), f.w - h2_hi(h1));
        *reinterpret_cast<uint2*>(sm + AH + off) = make_uint2(h0, h1);
        *reinterpret_cast<uint2*>(sm + AL + off) = make_uint2(l0, l1);
    }
}

// ---------------- kernel ----------------
__global__ void __launch_bounds__(THREADS, 1)
lfm_kernel(const float* __restrict__ state, const float* __restrict__ Wt,
           const float* __restrict__ bias,  float* __restrict__ out)
{
    extern __shared__ char sm[];
    uint32_t sbase = smem_u32(sm);
    const int tid  = threadIdx.x;
    const int wid  = tid >> 5;
    const int lane = tid & 31;
    const int wm   = wid & 3;       // warp m-block (32 rows each)
    const int wn   = wid >> 2;      // warp n-block (64 cols each)

    // ---- one-time: W[n][o][d] -> fp16 B smem (row index = o*128+n, k=d), bias to smem ----
    for (int idx = tid; idx < 128 * 128; idx += THREADS){
        int n = idx >> 7, d = idx & 127;
        #pragma unroll
        for (int o = 0; o < 2; o++){
            float w = Wt[(size_t)n * 256 + o * 128 + d];
            uint32_t off = (uint32_t)(o * 128 + n) * PITCH + d * 2;
            *reinterpret_cast<__half*>(sm + SM_B + off) = __float2half_rn(w);
        }
    }
    for (int idx = tid; idx < 256; idx += THREADS){
        int o = idx >> 7, n = idx & 127;
        reinterpret_cast<float*>(sm + SM_BIAS)[idx] = bias[n * 2 + o];
    }

    // per-lane ldmatrix sub-offsets
    const uint32_t aoff = (uint32_t)((lane & 7) + ((lane >> 3) & 1) * 8) * PITCH + ((lane >> 4) & 1) * 16;
    const uint32_t boff = (uint32_t)((lane & 7) + ((lane >> 4) & 1) * 8) * PITCH + ((lane >> 3) & 1) * 16;
    const uint32_t baseA0h = sbase + SM_A0_H + (uint32_t)(wm * 32) * PITCH + aoff;
    const uint32_t baseA0l = sbase + SM_A0_L + (uint32_t)(wm * 32) * PITCH + aoff;
    const uint32_t baseB   = sbase + SM_B    + (uint32_t)(wn * 64) * PITCH + boff;

    const int bid = blockIdx.x, grid = gridDim.x;
    const int nt  = (NTILES - bid + grid - 1) / grid;   // >= 1 since grid <= NTILES

    // Prologue: load + convert first tile into buffer 0
    float4 v[8];
    prefetch_tile(state, bid, tid, v);
    convert_tile(sm, 0, tid, v);
    __syncthreads();

    // Bias fragments -> registers (constant across tiles)
    const int o_half = wn >> 1;
    float bR0[8], bR1[8];
    {
        const float* bias_sm = reinterpret_cast<const float*>(sm + SM_BIAS);
        #pragma unroll
        for (int nj = 0; nj < 8; nj++){
            int cgb = (wn & 1) * 64 + nj * 8 + 2 * (lane & 3) + (o_half << 7);
            bR0[nj] = bias_sm[cgb];
            bR1[nj] = bias_sm[cgb + 1];
        }
    }

    const size_t out_half = (size_t)BATCH * DDIM;

    int cur = 0;
    for (int i = 0; i < nt; i++){
        const int  t   = bid + i * grid;
        const bool nxt = (i + 1) < nt;

        const uint32_t bAh = baseA0h + (uint32_t)(cur ? 69632 : 0);
        const uint32_t bAl = baseA0l + (uint32_t)(cur ? 69632 : 0);

        float acc[2][8][4];
        #pragma unroll
        for (int mt = 0; mt < 2; mt++)
            #pragma unroll
            for (int nj = 0; nj < 8; nj++)
                #pragma unroll
                for (int e = 0; e < 4; e++) acc[mt][nj][e] = 0.f;

        // ---- K loop: 8 steps of k16; 2-term fp16 split (sh*W + sl*W) ----
        #pragma unroll
        for (int ks = 0; ks < 8; ks++){
            uint32_t ah0[4], ah1[4], al0[4], al1[4];
            ldsm4(ah0, bAh + ks * 32);
            ldsm4(ah1, bAh + 16 * PITCH + ks * 32);
            ldsm4(al0, bAl + ks * 32);
            ldsm4(al1, bAl + 16 * PITCH + ks * 32);
            #pragma unroll
            for (int np = 0; np < 4; np++){        // pairs of n8 tiles
                uint32_t bw[4];
                ldsm4(bw, baseB + (uint32_t)(np * 16) * PITCH + ks * 32);
                mma16816(acc[0][2*np],   ah0, bw[0], bw[1]);
                mma16816(acc[1][2*np],   ah1, bw[0], bw[1]);
                mma16816(acc[0][2*np],   al0, bw[0], bw[1]);
                mma16816(acc[1][2*np],   al1, bw[0], bw[1]);
                mma16816(acc[0][2*np+1], ah0, bw[2], bw[3]);
                mma16816(acc[1][2*np+1], ah1, bw[2], bw[3]);
                mma16816(acc[0][2*np+1], al0, bw[2], bw[3]);
                mma16816(acc[1][2*np+1], al1, bw[2], bw[3]);
            }
        }

        // Prefetch next tile's state while the epilogue stores drain
        if (nxt) prefetch_tile(state, t + grid, tid, v);

        // ---- epilogue: bias + store. Warp covers rows [wm*32,+32), cols [wn*64,+64). ----
        {
            const int colw  = (wn & 1) * 64;
            const int rbase = wm * 32 + (lane >> 2);
            float* outp = out + (o_half ? out_half : 0) + ((size_t)t * TILE_M) * DDIM;
            #pragma unroll
            for (int mt = 0; mt < 2; mt++){
                #pragma unroll
                for (int nj = 0; nj < 8; nj++){
                    const int cg = colw + nj * 8 + 2 * (lane & 3);
                    float b0 = bR0[nj], b1 = bR1[nj];
                    float* p0 = outp + (size_t)(rbase + mt * 16) * DDIM + cg;
                    float* p1 = p0 + 8 * DDIM;
                    *reinterpret_cast<float2*>(p0) = make_float2(acc[mt][nj][0] + b0, acc[mt][nj][1] + b1);
                    *reinterpret_cast<float2*>(p1) = make_float2(acc[mt][nj][2] + b0, acc[mt][nj][3] + b1);
                }
            }
        }

        // Refill the other A buffer, then one sync before the next K-loop reads it.
        if (nxt){
            convert_tile(sm, cur ^ 1, tid, v);
            __syncthreads();
        }
        cur ^= 1;
    }
}

extern "C" void kernel_launch(void* const* d_in, const int* in_sizes, int n_in,
                              void* d_out, int out_size){
    (void)in_sizes; (void)n_in; (void)out_size;
    const float* state = (const float*)d_in[0];
    const float* W     = (const float*)d_in[1];
    const float* b     = (const float*)d_in[2];
    float* out = (float*)d_out;

    int dev = 0, sms = 148;
    cudaGetDevice(&dev);
    cudaDeviceGetAttribute(&sms, cudaDevAttrMultiProcessorCount, dev);
    if (sms < 1) sms = 148;
    if (sms > NTILES) sms = NTILES;

    cudaFuncSetAttribute(lfm_kernel, cudaFuncAttributeMaxDynamicSharedMemorySize, SMEM_TOTAL);
    lfm_kernel<<<sms, THREADS, SMEM_TOTAL>>>(state, W, b, out);
}

// round 4
// speedup vs baseline: 1.4596x; 1.2472x over previous
#include <cuda_runtime.h>
#include <cuda_fp16.h>
#include <cstdint>

#define THREADS 512
static constexpr int BATCH  = 131072;
static constexpr int DDIM   = 128;
static constexpr int TILE_M = 128;
static constexpr int NTILES = BATCH / TILE_M;   // 1024
static constexpr int PITCH  = 272;              // 128 fp16 (256B) + 16B pad -> conflict-free ldmatrix

// ---- SMEM layout (bytes). A fp16 double-buffered; B single fp16. ----
static constexpr int SM_A0   = 0;               // 128 x PITCH = 34816
static constexpr int SM_A1   = 34816;
static constexpr int SM_B    = 69632;           // 256 x PITCH = 69632
static constexpr int SM_BIAS = 139264;          // 256 floats
static constexpr int SMEM_TOTAL = 139264 + 1024;

// ---------------- helpers ----------------
__device__ __forceinline__ uint32_t smem_u32(const void* p){
    uint32_t a;
    asm("{ .reg .u64 t; cvta.to.shared.u64 t, %1; cvt.u32.u64 %0, t; }" : "=r"(a) : "l"(p));
    return a;
}
__device__ __forceinline__ void ldsm4(uint32_t* r, uint32_t addr){
    asm volatile("ldmatrix.sync.aligned.m8n8.x4.shared.b16 {%0,%1,%2,%3}, [%4];"
        : "=r"(r[0]), "=r"(r[1]), "=r"(r[2]), "=r"(r[3]) : "r"(addr));
}
__device__ __forceinline__ void mma16816(float* c, const uint32_t* a, uint32_t b0, uint32_t b1){
    asm("mma.sync.aligned.m16n8k16.row.col.f32.f16.f16.f32 "
        "{%0,%1,%2,%3}, {%4,%5,%6,%7}, {%8,%9}, {%0,%1,%2,%3};"
        : "+f"(c[0]), "+f"(c[1]), "+f"(c[2]), "+f"(c[3])
        : "r"(a[0]), "r"(a[1]), "r"(a[2]), "r"(a[3]), "r"(b0), "r"(b1));
}
__device__ __forceinline__ uint32_t pack_h2(float lo, float hi){
    __half2 h = __floats2half2_rn(lo, hi);
    return *reinterpret_cast<uint32_t*>(&h);
}

// ---------------- tile helpers ----------------
__device__ __forceinline__ void prefetch_tile(const float* __restrict__ state, int t, int tid, float4* v){
    const float4* p = reinterpret_cast<const float4*>(state) + (size_t)t * (TILE_M * DDIM / 4);
    #pragma unroll
    for (int k = 0; k < 8; k++) v[k] = p[tid + THREADS * k];
}

// fp32 -> fp16 conversion of the 128x128 state tile into A smem (row pitch 272B).
__device__ __forceinline__ void convert_tile(char* sm, int buf, int tid, const float4* v){
    const int AH = buf ? SM_A1 : SM_A0;
    #pragma unroll
    for (int k = 0; k < 8; k++){
        int j  = tid + THREADS * k;           // float4 index within tile
        int r  = j >> 5;                      // row (32 float4 per row)
        int cb = (j & 31) * 8;                // byte col within 256B of fp16 data
        uint32_t off = (uint32_t)r * PITCH + cb;
        float4 f = v[k];
        uint32_t h0 = pack_h2(f.x, f.y);
        uint32_t h1 = pack_h2(f.z, f.w);
        *reinterpret_cast<uint2*>(sm + AH + off) = make_uint2(h0, h1);
    }
}

// ---------------- kernel ----------------
__global__ void __launch_bounds__(THREADS, 1)
lfm_kernel(const float* __restrict__ state, const float* __restrict__ Wt,
           const float* __restrict__ bias,  float* __restrict__ out)
{
    extern __shared__ char sm[];
    uint32_t sbase = smem_u32(sm);
    const int tid  = threadIdx.x;
    const int wid  = tid >> 5;
    const int lane = tid & 31;
    const int wm   = wid & 3;       // warp m-block (32 rows each)
    const int wn   = wid >> 2;      // warp n-block (64 cols each)

    // ---- one-time: W[n][o][d] -> fp16 B smem (row index = o*128+n, k=d), bias to smem ----
    for (int idx = tid; idx < 128 * 128; idx += THREADS){
        int n = idx >> 7, d = idx & 127;
        #pragma unroll
        for (int o = 0; o < 2; o++){
            float w = Wt[(size_t)n * 256 + o * 128 + d];
            uint32_t off = (uint32_t)(o * 128 + n) * PITCH + d * 2;
            *reinterpret_cast<__half*>(sm + SM_B + off) = __float2half_rn(w);
        }
    }
    for (int idx = tid; idx < 256; idx += THREADS){
        int o = idx >> 7, n = idx & 127;
        reinterpret_cast<float*>(sm + SM_BIAS)[idx] = bias[n * 2 + o];
    }

    // per-lane ldmatrix sub-offsets
    const uint32_t aoff = (uint32_t)((lane & 7) + ((lane >> 3) & 1) * 8) * PITCH + ((lane >> 4) & 1) * 16;
    const uint32_t boff = (uint32_t)((lane & 7) + ((lane >> 4) & 1) * 8) * PITCH + ((lane >> 3) & 1) * 16;
    const uint32_t baseA0 = sbase + SM_A0 + (uint32_t)(wm * 32) * PITCH + aoff;
    const uint32_t baseB  = sbase + SM_B  + (uint32_t)(wn * 64) * PITCH + boff;

    const int bid = blockIdx.x, grid = gridDim.x;
    const int nt  = (NTILES - bid + grid - 1) / grid;   // >= 1 since grid <= NTILES

    // Prologue: load + convert first tile into buffer 0
    float4 v[8];
    prefetch_tile(state, bid, tid, v);
    convert_tile(sm, 0, tid, v);
    __syncthreads();

    // Bias fragments -> registers (constant across tiles)
    const int o_half = wn >> 1;
    float bR0[8], bR1[8];
    {
        const float* bias_sm = reinterpret_cast<const float*>(sm + SM_BIAS);
        #pragma unroll
        for (int nj = 0; nj < 8; nj++){
            int cgb = (wn & 1) * 64 + nj * 8 + 2 * (lane & 3) + (o_half << 7);
            bR0[nj] = bias_sm[cgb];
            bR1[nj] = bias_sm[cgb + 1];
        }
    }

    const size_t out_half = (size_t)BATCH * DDIM;

    int cur = 0;
    for (int i = 0; i < nt; i++){
        const int  t   = bid + i * grid;
        const bool nxt = (i + 1) < nt;

        const uint32_t bA = baseA0 + (uint32_t)(cur ? SM_A1 : 0);

        float acc[2][8][4];
        #pragma unroll
        for (int mt = 0; mt < 2; mt++)
            #pragma unroll
            for (int nj = 0; nj < 8; nj++)
                #pragma unroll
                for (int e = 0; e < 4; e++) acc[mt][nj][e] = 0.f;

        // ---- K loop: 8 steps of k16, single fp16 term ----
        #pragma unroll
        for (int ks = 0; ks < 8; ks++){
            uint32_t a0[4], a1[4];
            ldsm4(a0, bA + ks * 32);
            ldsm4(a1, bA + 16 * PITCH + ks * 32);
            #pragma unroll
            for (int np = 0; np < 4; np++){        // pairs of n8 tiles
                uint32_t bw[4];
                ldsm4(bw, baseB + (uint32_t)(np * 16) * PITCH + ks * 32);
                mma16816(acc[0][2*np],   a0, bw[0], bw[1]);
                mma16816(acc[1][2*np],   a1, bw[0], bw[1]);
                mma16816(acc[0][2*np+1], a0, bw[2], bw[3]);
                mma16816(acc[1][2*np+1], a1, bw[2], bw[3]);
            }
        }

        // Prefetch next tile's state; DRAM latency hidden behind epilogue stores.
        if (nxt) prefetch_tile(state, t + grid, tid, v);

        // ---- epilogue: bias + store. Warp covers rows [wm*32,+32), cols [wn*64,+64). ----
        {
            const int colw  = (wn & 1) * 64;
            const int rbase = wm * 32 + (lane >> 2);
            float* outp = out + (o_half ? out_half : 0) + ((size_t)t * TILE_M) * DDIM;
            #pragma unroll
            for (int mt = 0; mt < 2; mt++){
                #pragma unroll
                for (int nj = 0; nj < 8; nj++){
                    const int cg = colw + nj * 8 + 2 * (lane & 3);
                    float b0 = bR0[nj], b1 = bR1[nj];
                    float* p0 = outp + (size_t)(rbase + mt * 16) * DDIM + cg;
                    float* p1 = p0 + 8 * DDIM;
                    *reinterpret_cast<float2*>(p0) = make_float2(acc[mt][nj][0] + b0, acc[mt][nj][1] + b1);
                    *reinterpret_cast<float2*>(p1) = make_float2(acc[mt][nj][2] + b0, acc[mt][nj][3] + b1);
                }
            }
        }

        // Refill the other A buffer, then one sync before the next K-loop reads it.
        if (nxt){
            convert_tile(sm, cur ^ 1, tid, v);
            __syncthreads();
        }
        cur ^= 1;
    }
}

extern "C" void kernel_launch(void* const* d_in, const int* in_sizes, int n_in,
                              void* d_out, int out_size){
    (void)in_sizes; (void)n_in; (void)out_size;
    const float* state = (const float*)d_in[0];
    const float* W     = (const float*)d_in[1];
    const float* b     = (const float*)d_in[2];
    float* out = (float*)d_out;

    int dev = 0, sms = 148;
    cudaGetDevice(&dev);
    cudaDeviceGetAttribute(&sms, cudaDevAttrMultiProcessorCount, dev);
    if (sms < 1) sms = 148;
    if (sms > NTILES) sms = NTILES;

    cudaFuncSetAttribute(lfm_kernel, cudaFuncAttributeMaxDynamicSharedMemorySize, SMEM_TOTAL);
    lfm_kernel<<<sms, THREADS, SMEM_TOTAL>>>(state, W, b, out);
}